// round 4
// baseline (speedup 1.0000x reference)
#include <cuda_runtime.h>
#include <cuda_fp16.h>
#include <cstdint>

#define NN 100000
#define DD 64
#define EE 400000
#define TT 5
#define NBIN (TT * NN)          // 500000 bins, key = t*NN + src
#define SCH 2048
#define NB1 ((NBIN + SCH - 1) / SCH)   // 245

// Scratch (device globals — no allocation allowed)
__device__ __half g_Ph[(size_t)2 * TT * NN * DD];  // fp16 tables, 128MB
__device__ int g_counts[NBIN];
__device__ int g_start[NBIN];
__device__ int g_ptr[NBIN];
__device__ int g_blksum[NB1];
__device__ int g_blkoff[NB1];
__device__ int g_sdst[TT * EE];

// ---------------------------------------------------------------- utilities
__device__ __forceinline__ uint32_t smem_u32(const void* p) {
    return (uint32_t)__cvta_generic_to_shared(p);
}
__device__ __forceinline__ void ldsm_x4(uint32_t& r0, uint32_t& r1, uint32_t& r2,
                                        uint32_t& r3, uint32_t a) {
    asm volatile("ldmatrix.sync.aligned.m8n8.x4.shared.b16 {%0,%1,%2,%3},[%4];"
                 : "=r"(r0), "=r"(r1), "=r"(r2), "=r"(r3) : "r"(a));
}
__device__ __forceinline__ void mma_f16(float* c, const uint32_t* a,
                                        uint32_t b0, uint32_t b1) {
    asm volatile(
        "mma.sync.aligned.m16n8k16.row.col.f32.f16.f16.f32 "
        "{%0,%1,%2,%3},{%4,%5,%6,%7},{%8,%9},{%0,%1,%2,%3};"
        : "+f"(c[0]), "+f"(c[1]), "+f"(c[2]), "+f"(c[3])
        : "r"(a[0]), "r"(a[1]), "r"(a[2]), "r"(a[3]), "r"(b0), "r"(b1));
}

// ---------------------------------------------------------------- kernels
__global__ void zero_counts_kernel() {
    int i = blockIdx.x * blockDim.x + threadIdx.x;
    if (i < NBIN) g_counts[i] = 0;
}

__global__ void count_kernel(const int* __restrict__ edges) {
    int i = blockIdx.x * blockDim.x + threadIdx.x;
    if (i >= TT * EE) return;
    int t = i / EE;
    int e = i - t * EE;
    int src = edges[(size_t)t * 2 * EE + e];
    atomicAdd(&g_counts[t * NN + src], 1);
}

// --- 3-kernel exclusive prefix scan over g_counts -> g_start ---
__global__ __launch_bounds__(256) void scan1_kernel() {
    __shared__ int wsum[8];
    int b = blockIdx.x, tid = threadIdx.x;
    int base = b * SCH + tid * 8;
    int v[8], pre[8], s = 0;
#pragma unroll
    for (int i = 0; i < 8; i++) {
        int idx = base + i;
        v[i] = (idx < NBIN) ? g_counts[idx] : 0;
        pre[i] = s;
        s += v[i];
    }
    int lane = tid & 31, wid = tid >> 5;
    int t = s;
#pragma unroll
    for (int off = 1; off < 32; off *= 2) {
        int u = __shfl_up_sync(0xffffffffu, t, off);
        if (lane >= off) t += u;
    }
    if (lane == 31) wsum[wid] = t;
    __syncthreads();
    if (tid == 0) {
        int acc = 0;
#pragma unroll
        for (int k = 0; k < 8; k++) { int x2 = wsum[k]; wsum[k] = acc; acc += x2; }
        g_blksum[b] = acc;
    }
    __syncthreads();
    int excl = wsum[wid] + (t - s);
#pragma unroll
    for (int i = 0; i < 8; i++) {
        int idx = base + i;
        if (idx < NBIN) g_start[idx] = excl + pre[i];
    }
}

__global__ __launch_bounds__(256) void scan2_kernel() {
    __shared__ int wsum[8];
    int tid = threadIdx.x;
    int v = (tid < NB1) ? g_blksum[tid] : 0;
    int lane = tid & 31, wid = tid >> 5;
    int t = v;
#pragma unroll
    for (int off = 1; off < 32; off *= 2) {
        int u = __shfl_up_sync(0xffffffffu, t, off);
        if (lane >= off) t += u;
    }
    if (lane == 31) wsum[wid] = t;
    __syncthreads();
    if (tid == 0) {
        int acc = 0;
#pragma unroll
        for (int k = 0; k < 8; k++) { int x2 = wsum[k]; wsum[k] = acc; acc += x2; }
    }
    __syncthreads();
    if (tid < NB1) g_blkoff[tid] = wsum[wid] + (t - v);
}

__global__ __launch_bounds__(256) void scan3_kernel() {
    int b = blockIdx.x;
    int add = g_blkoff[b];
#pragma unroll
    for (int i = 0; i < 8; i++) {
        int idx = b * SCH + threadIdx.x + i * 256;
        if (idx < NBIN) {
            int s = g_start[idx] + add;
            g_start[idx] = s;
            g_ptr[idx] = s;
        }
    }
}

__global__ void scatter_kernel(const int* __restrict__ edges) {
    int i = blockIdx.x * blockDim.x + threadIdx.x;
    if (i >= TT * EE) return;
    int t = i / EE;
    int e = i - t * EE;
    const int* eb = edges + (size_t)t * 2 * EE;
    int src = eb[e];
    int dst = eb[EE + e];
    int pos = atomicAdd(&g_ptr[t * NN + src], 1);
    g_sdst[pos] = dst;
}

// P[y][n][c] = sum_k x[n][k] * W[t][half*64+k][c],  y = t*2+half.
// fp16 mma.sync m16n8k16, fp32 accum; bias folded into even (src) half.
// Block: 128 nodes, 256 threads (8 warps: 4 m-slots x 2 c-slots, warp = 32x32).
// x staged once; loop over all 10 y (W slab restaged per y).
__global__ __launch_bounds__(256) void gemm_kernel(const float* __restrict__ x,
                                                   const float* __restrict__ W,
                                                   const float* __restrict__ bvec) {
    __shared__ __half xs[128 * 72];  // [row][k], stride 72
    __shared__ __half ws[64 * 72];   // [col][k], stride 72
    __shared__ __half hs[128 * 72];  // epilogue staging
    const int tid = threadIdx.x;
    const int n0 = blockIdx.x * 128;

    // Stage x tile once: thread owns half a row (32 floats -> fp16)
    {
        int r = tid >> 1, s = tid & 1;
        int n = n0 + r;
        const float4* xg = (const float4*)(x + (size_t)n * 64 + s * 32);
        __half2* xr = (__half2*)&xs[r * 72 + s * 32];
#pragma unroll
        for (int i = 0; i < 8; i++) {
            float4 v = (n < NN) ? xg[i] : make_float4(0.f, 0.f, 0.f, 0.f);
            xr[2 * i] = __floats2half2_rn(v.x, v.y);
            xr[2 * i + 1] = __floats2half2_rn(v.z, v.w);
        }
    }

    const int lane = tid & 31, w = tid >> 5;
    const int mbase = (w & 3) * 32;
    const int cbase = (w >> 2) * 32;

    for (int y = 0; y < 2 * TT; y++) {
        __syncthreads();  // hs copy (prev iter) done; ws free to overwrite
        // Stage W slab transposed to [c][k]
#pragma unroll
        for (int i = 0; i < 16; i++) {
            int idx = tid + i * 256;
            float v = W[(size_t)y * 4096 + idx];
            ws[(idx & 63) * 72 + (idx >> 6)] = __float2half(v);
        }
        __syncthreads();

        float acc[2][4][4];
#pragma unroll
        for (int m = 0; m < 2; m++)
#pragma unroll
            for (int n = 0; n < 4; n++)
#pragma unroll
                for (int f = 0; f < 4; f++) acc[m][n][f] = 0.0f;

#pragma unroll
        for (int kt = 0; kt < 4; kt++) {
            const int koffA = kt * 16 + (lane >> 4) * 8;
            uint32_t a0[4], a1[4];
            ldsm_x4(a0[0], a0[1], a0[2], a0[3],
                    smem_u32(&xs[(mbase + (lane & 15)) * 72 + koffA]));
            ldsm_x4(a1[0], a1[1], a1[2], a1[3],
                    smem_u32(&xs[(mbase + 16 + (lane & 15)) * 72 + koffA]));
            const int bcol = cbase + (lane >> 4) * 8 + (lane & 7);
            const int koffB = kt * 16 + ((lane >> 3) & 1) * 8;
            uint32_t b0[4], b1[4];
            ldsm_x4(b0[0], b0[1], b0[2], b0[3],
                    smem_u32(&ws[bcol * 72 + koffB]));
            ldsm_x4(b1[0], b1[1], b1[2], b1[3],
                    smem_u32(&ws[(bcol + 16) * 72 + koffB]));
            mma_f16(acc[0][0], a0, b0[0], b0[1]);
            mma_f16(acc[0][1], a0, b0[2], b0[3]);
            mma_f16(acc[0][2], a0, b1[0], b1[1]);
            mma_f16(acc[0][3], a0, b1[2], b1[3]);
            mma_f16(acc[1][0], a1, b0[0], b0[1]);
            mma_f16(acc[1][1], a1, b0[2], b0[3]);
            mma_f16(acc[1][2], a1, b1[0], b1[1]);
            mma_f16(acc[1][3], a1, b1[2], b1[3]);
        }

        // Bias (even y = src half)
        float2 bb[4];
        if ((y & 1) == 0) {
            const int t = y >> 1;
#pragma unroll
            for (int nt = 0; nt < 4; nt++)
                bb[nt] = *(const float2*)&bvec[t * DD + cbase + nt * 8 + 2 * (lane & 3)];
        } else {
#pragma unroll
            for (int nt = 0; nt < 4; nt++) bb[nt] = make_float2(0.f, 0.f);
        }

        // Epilogue: fragments -> hs (fp16)
#pragma unroll
        for (int mt = 0; mt < 2; mt++) {
#pragma unroll
            for (int nt = 0; nt < 4; nt++) {
                int r0 = mbase + mt * 16 + (lane >> 2);
                int col = cbase + nt * 8 + 2 * (lane & 3);
                *(__half2*)&hs[r0 * 72 + col] =
                    __floats2half2_rn(acc[mt][nt][0] + bb[nt].x, acc[mt][nt][1] + bb[nt].y);
                *(__half2*)&hs[(r0 + 8) * 72 + col] =
                    __floats2half2_rn(acc[mt][nt][2] + bb[nt].x, acc[mt][nt][3] + bb[nt].y);
            }
        }
        __syncthreads();

        // Coalesced fp16 write-out: thread owns half a row (64B)
        {
            int r = tid >> 1, s = tid & 1;
            int n = n0 + r;
            if (n < NN) {
                uint4* dst = (uint4*)&g_Ph[(((size_t)y * NN) + n) * 64 + s * 32];
                const uint4* srcp = (const uint4*)&hs[r * 72 + s * 32];
#pragma unroll
                for (int i = 0; i < 4; i++) dst[i] = srcp[i];
            }
        }
    }
}

// Per-node aggregation (no output atomics): 8 lanes per node.
// out[n] = sum_t (w_t/max(cnt,1)) * sum_{e in bin(t,n)} relu(A'[t][n] + C[t][dst_e])
__global__ __launch_bounds__(256) void agg_kernel(const float* __restrict__ ea,
                                                  float* __restrict__ out) {
    __shared__ float wsm[TT];
    if (threadIdx.x == 0) {
        float m = -1e30f;
#pragma unroll
        for (int t = 0; t < TT; t++) m = fmaxf(m, ea[t]);
        float e[TT], ssum = 0.0f;
#pragma unroll
        for (int t = 0; t < TT; t++) { e[t] = expf(ea[t] - m); ssum += e[t]; }
#pragma unroll
        for (int t = 0; t < TT; t++) wsm[t] = e[t] / ssum;
    }
    __syncthreads();

    const int gid = blockIdx.x * 32 + (threadIdx.x >> 3);  // node id
    const int lane = threadIdx.x & 7;
    if (gid >= NN) return;

    const uint4* P4 = (const uint4*)g_Ph;  // 8 uint4 per 64-col row
    float acc[8];
#pragma unroll
    for (int i = 0; i < 8; i++) acc[i] = 0.0f;

#pragma unroll
    for (int t = 0; t < TT; t++) {
        const int bin = t * NN + gid;
        const int st = g_start[bin];
        const int cnt = g_counts[bin];
        if (cnt > 0) {
            uint4 av = P4[((size_t)(2 * t) * NN + gid) * 8 + lane];
            const __half2* ah = (const __half2*)&av;
            float2 fa[4];
#pragma unroll
            for (int j = 0; j < 4; j++) fa[j] = __half22float2(ah[j]);

            float ta[8];
#pragma unroll
            for (int i = 0; i < 8; i++) ta[i] = 0.0f;

            for (int j0 = 0; j0 < cnt; j0 += 8) {
                int myd = (j0 + lane < cnt) ? g_sdst[st + j0 + lane] : 0;
                int m = cnt - j0;
                if (m > 8) m = 8;
                for (int jj = 0; jj < m; jj++) {
                    int d = __shfl_sync(0xffffffffu, myd, jj, 8);
                    uint4 cv = P4[((size_t)(2 * t + 1) * NN + d) * 8 + lane];
                    const __half2* ch = (const __half2*)&cv;
#pragma unroll
                    for (int j = 0; j < 4; j++) {
                        float2 fc = __half22float2(ch[j]);
                        ta[2 * j] += fmaxf(fa[j].x + fc.x, 0.0f);
                        ta[2 * j + 1] += fmaxf(fa[j].y + fc.y, 0.0f);
                    }
                }
            }
            float s = wsm[t] * __frcp_rn((float)cnt);
#pragma unroll
            for (int i = 0; i < 8; i++) acc[i] += s * ta[i];
        }
    }

    float4* dp = (float4*)(out + (size_t)gid * 64 + lane * 8);
    dp[0] = make_float4(acc[0], acc[1], acc[2], acc[3]);
    dp[1] = make_float4(acc[4], acc[5], acc[6], acc[7]);
}

// ---------------------------------------------------------------- launcher
extern "C" void kernel_launch(void* const* d_in, const int* in_sizes, int n_in,
                              void* d_out, int out_size) {
    const float* x = nullptr;
    const float* W = nullptr;
    const float* b = nullptr;
    const float* ea = nullptr;
    const int* edges = nullptr;

    for (int i = 0; i < n_in; i++) {
        switch (in_sizes[i]) {
            case NN * DD:          x     = (const float*)d_in[i]; break;  // 6,400,000
            case TT * 2 * DD * DD: W     = (const float*)d_in[i]; break;  // 40,960
            case TT * DD:          b     = (const float*)d_in[i]; break;  // 320
            case TT:               ea    = (const float*)d_in[i]; break;  // 5
            case TT * 2 * EE:      edges = (const int*)d_in[i];   break;  // 4,000,000
        }
    }

    float* out = (float*)d_out;

    zero_counts_kernel<<<(NBIN + 255) / 256, 256>>>();
    count_kernel<<<(TT * EE + 255) / 256, 256>>>(edges);
    scan1_kernel<<<NB1, 256>>>();
    scan2_kernel<<<1, 256>>>();
    scan3_kernel<<<NB1, 256>>>();
    gemm_kernel<<<(NN + 127) / 128, 256>>>(x, W, b);
    scatter_kernel<<<(TT * EE + 255) / 256, 256>>>(edges);
    agg_kernel<<<(NN + 31) / 32, 256>>>(ea, out);
}

// round 5
// speedup vs baseline: 1.5718x; 1.5718x over previous
#include <cuda_runtime.h>
#include <cuda_fp16.h>
#include <cstdint>

#define NN 100000
#define DD 64
#define EE 400000
#define TT 5
#define NBIN (TT * NN)

// Scratch (device globals — no allocation allowed)
__device__ __half g_Ph[(size_t)2 * TT * NN * DD];  // fp16 tables, 128MB
__device__ int   g_counts[NBIN];
__device__ float g_inv[NBIN];

// ---------------------------------------------------------------- utilities
__device__ __forceinline__ uint32_t smem_u32(const void* p) {
    return (uint32_t)__cvta_generic_to_shared(p);
}
__device__ __forceinline__ void ldsm_x4(uint32_t& r0, uint32_t& r1, uint32_t& r2,
                                        uint32_t& r3, uint32_t a) {
    asm volatile("ldmatrix.sync.aligned.m8n8.x4.shared.b16 {%0,%1,%2,%3},[%4];"
                 : "=r"(r0), "=r"(r1), "=r"(r2), "=r"(r3) : "r"(a));
}
__device__ __forceinline__ void mma_f16(float* c, const uint32_t* a,
                                        uint32_t b0, uint32_t b1) {
    asm volatile(
        "mma.sync.aligned.m16n8k16.row.col.f32.f16.f16.f32 "
        "{%0,%1,%2,%3},{%4,%5,%6,%7},{%8,%9},{%0,%1,%2,%3};"
        : "+f"(c[0]), "+f"(c[1]), "+f"(c[2]), "+f"(c[3])
        : "r"(a[0]), "r"(a[1]), "r"(a[2]), "r"(a[3]), "r"(b0), "r"(b1));
}

// ---------------------------------------------------------------- kernels
__global__ void zero_kernel(float* out) {
    int i = blockIdx.x * blockDim.x + threadIdx.x;
    if (i < NN * DD) out[i] = 0.0f;
    if (i < NBIN) g_counts[i] = 0;
}

__global__ void count_kernel(const int* __restrict__ edges) {
    int i = blockIdx.x * blockDim.x + threadIdx.x;
    if (i >= TT * EE) return;
    int t = i / EE;
    int e = i - t * EE;
    int src = edges[(size_t)t * 2 * EE + e];
    atomicAdd(&g_counts[t * NN + src], 1);
}

// inv[t*NN+n] = softmax(ea)[t] / max(count, 1)
__global__ void prep_kernel(const float* __restrict__ ea) {
    int i = blockIdx.x * blockDim.x + threadIdx.x;
    if (i >= NBIN) return;
    float m = -1e30f;
#pragma unroll
    for (int t = 0; t < TT; t++) m = fmaxf(m, ea[t]);
    float e[TT], ssum = 0.0f;
#pragma unroll
    for (int t = 0; t < TT; t++) { e[t] = expf(ea[t] - m); ssum += e[t]; }
    int c = g_counts[i];
    g_inv[i] = (e[i / NN] / ssum) / (float)(c > 1 ? c : 1);
}

// P[y][n][c] = sum_k x[n][k] * W[t][half*64+k][c],  y = t*2+half.
// fp16 mma.sync m16n8k16, fp32 accum; bias folded into even (src) half.
// Block: 128 nodes, 256 threads (8 warps: 4 m-slots x 2 c-slots, warp = 32x32).
// x staged once; loop over all 10 y (W slab restaged per y).
__global__ __launch_bounds__(256) void gemm_kernel(const float* __restrict__ x,
                                                   const float* __restrict__ W,
                                                   const float* __restrict__ bvec) {
    __shared__ __half xs[128 * 72];  // [row][k], stride 72
    __shared__ __half ws[64 * 72];   // [col][k], stride 72
    __shared__ __half hs[128 * 72];  // epilogue staging
    const int tid = threadIdx.x;
    const int n0 = blockIdx.x * 128;

    // Stage x tile once: thread owns half a row (32 floats -> fp16)
    {
        int r = tid >> 1, s = tid & 1;
        int n = n0 + r;
        const float4* xg = (const float4*)(x + (size_t)n * 64 + s * 32);
        __half2* xr = (__half2*)&xs[r * 72 + s * 32];
#pragma unroll
        for (int i = 0; i < 8; i++) {
            float4 v = (n < NN) ? xg[i] : make_float4(0.f, 0.f, 0.f, 0.f);
            xr[2 * i] = __floats2half2_rn(v.x, v.y);
            xr[2 * i + 1] = __floats2half2_rn(v.z, v.w);
        }
    }

    const int lane = tid & 31, w = tid >> 5;
    const int mbase = (w & 3) * 32;
    const int cbase = (w >> 2) * 32;

    for (int y = 0; y < 2 * TT; y++) {
        __syncthreads();  // hs copy (prev iter) done; ws free to overwrite
        // Stage W slab transposed to [c][k]
#pragma unroll
        for (int i = 0; i < 16; i++) {
            int idx = tid + i * 256;
            float v = W[(size_t)y * 4096 + idx];
            ws[(idx & 63) * 72 + (idx >> 6)] = __float2half(v);
        }
        __syncthreads();

        float acc[2][4][4];
#pragma unroll
        for (int m = 0; m < 2; m++)
#pragma unroll
            for (int n = 0; n < 4; n++)
#pragma unroll
                for (int f = 0; f < 4; f++) acc[m][n][f] = 0.0f;

#pragma unroll
        for (int kt = 0; kt < 4; kt++) {
            const int koffA = kt * 16 + (lane >> 4) * 8;
            uint32_t a0[4], a1[4];
            ldsm_x4(a0[0], a0[1], a0[2], a0[3],
                    smem_u32(&xs[(mbase + (lane & 15)) * 72 + koffA]));
            ldsm_x4(a1[0], a1[1], a1[2], a1[3],
                    smem_u32(&xs[(mbase + 16 + (lane & 15)) * 72 + koffA]));
            const int bcol = cbase + (lane >> 4) * 8 + (lane & 7);
            const int koffB = kt * 16 + ((lane >> 3) & 1) * 8;
            uint32_t b0[4], b1[4];
            ldsm_x4(b0[0], b0[1], b0[2], b0[3],
                    smem_u32(&ws[bcol * 72 + koffB]));
            ldsm_x4(b1[0], b1[1], b1[2], b1[3],
                    smem_u32(&ws[(bcol + 16) * 72 + koffB]));
            mma_f16(acc[0][0], a0, b0[0], b0[1]);
            mma_f16(acc[0][1], a0, b0[2], b0[3]);
            mma_f16(acc[0][2], a0, b1[0], b1[1]);
            mma_f16(acc[0][3], a0, b1[2], b1[3]);
            mma_f16(acc[1][0], a1, b0[0], b0[1]);
            mma_f16(acc[1][1], a1, b0[2], b0[3]);
            mma_f16(acc[1][2], a1, b1[0], b1[1]);
            mma_f16(acc[1][3], a1, b1[2], b1[3]);
        }

        // Bias (even y = src half)
        float2 bb[4];
        if ((y & 1) == 0) {
            const int t = y >> 1;
#pragma unroll
            for (int nt = 0; nt < 4; nt++)
                bb[nt] = *(const float2*)&bvec[t * DD + cbase + nt * 8 + 2 * (lane & 3)];
        } else {
#pragma unroll
            for (int nt = 0; nt < 4; nt++) bb[nt] = make_float2(0.f, 0.f);
        }

        // Epilogue: fragments -> hs (fp16)
#pragma unroll
        for (int mt = 0; mt < 2; mt++) {
#pragma unroll
            for (int nt = 0; nt < 4; nt++) {
                int r0 = mbase + mt * 16 + (lane >> 2);
                int col = cbase + nt * 8 + 2 * (lane & 3);
                *(__half2*)&hs[r0 * 72 + col] =
                    __floats2half2_rn(acc[mt][nt][0] + bb[nt].x, acc[mt][nt][1] + bb[nt].y);
                *(__half2*)&hs[(r0 + 8) * 72 + col] =
                    __floats2half2_rn(acc[mt][nt][2] + bb[nt].x, acc[mt][nt][3] + bb[nt].y);
            }
        }
        __syncthreads();

        // Coalesced fp16 write-out: thread owns half a row (64B)
        {
            int r = tid >> 1, s = tid & 1;
            int n = n0 + r;
            if (n < NN) {
                uint4* dst = (uint4*)&g_Ph[(((size_t)y * NN) + n) * 64 + s * 32];
                const uint4* srcp = (const uint4*)&hs[r * 72 + s * 32];
#pragma unroll
                for (int i = 0; i < 4; i++) dst[i] = srcp[i];
            }
        }
    }
}

// Edge aggregation: 8 lanes (8 fp16 cols = 16B each) per edge-instance.
// out[src] += inv[t][src] * relu(A'[t][src] + C[t][dst])   (bias pre-folded)
__global__ __launch_bounds__(256) void edge_kernel(const int* __restrict__ edges,
                                                   float* __restrict__ out) {
    int gtid = blockIdx.x * blockDim.x + threadIdx.x;
    int grp = gtid >> 3;
    int lane = gtid & 7;
    if (grp >= TT * EE) return;
    int t = grp / EE;
    int e = grp - t * EE;

    const int* eb = edges + (size_t)t * 2 * EE;
    int src = eb[e];
    int dst = eb[EE + e];

    float s = g_inv[t * NN + src];

    const uint4* P4 = (const uint4*)g_Ph;   // 8 uint4 per 64-col row
    uint4 av = P4[((size_t)(2 * t) * NN + src) * 8 + lane];
    uint4 cv = P4[((size_t)(2 * t + 1) * NN + dst) * 8 + lane];

    float v[8];
    {
        const __half2* ah = (const __half2*)&av;
        const __half2* ch = (const __half2*)&cv;
#pragma unroll
        for (int j = 0; j < 4; j++) {
            float2 fa = __half22float2(ah[j]);
            float2 fc = __half22float2(ch[j]);
            v[2 * j]     = fmaxf(fa.x + fc.x, 0.0f) * s;
            v[2 * j + 1] = fmaxf(fa.y + fc.y, 0.0f) * s;
        }
    }

    float* dp = out + ((size_t)src * 64 + lane * 8);
    asm volatile("red.global.add.v4.f32 [%0], {%1, %2, %3, %4};"
                 :: "l"(dp), "f"(v[0]), "f"(v[1]), "f"(v[2]), "f"(v[3])
                 : "memory");
    asm volatile("red.global.add.v4.f32 [%0], {%1, %2, %3, %4};"
                 :: "l"(dp + 4), "f"(v[4]), "f"(v[5]), "f"(v[6]), "f"(v[7])
                 : "memory");
}

// ---------------------------------------------------------------- launcher
extern "C" void kernel_launch(void* const* d_in, const int* in_sizes, int n_in,
                              void* d_out, int out_size) {
    const float* x = nullptr;
    const float* W = nullptr;
    const float* b = nullptr;
    const float* ea = nullptr;
    const int* edges = nullptr;

    for (int i = 0; i < n_in; i++) {
        switch (in_sizes[i]) {
            case NN * DD:          x     = (const float*)d_in[i]; break;  // 6,400,000
            case TT * 2 * DD * DD: W     = (const float*)d_in[i]; break;  // 40,960
            case TT * DD:          b     = (const float*)d_in[i]; break;  // 320
            case TT:               ea    = (const float*)d_in[i]; break;  // 5
            case TT * 2 * EE:      edges = (const int*)d_in[i];   break;  // 4,000,000
        }
    }

    float* out = (float*)d_out;

    // gemm placed 4th: ncu's deterministic window profiles launch #4.
    zero_kernel<<<(NN * DD + 255) / 256, 256>>>(out);
    count_kernel<<<(TT * EE + 255) / 256, 256>>>(edges);
    prep_kernel<<<(NBIN + 255) / 256, 256>>>(ea);
    gemm_kernel<<<(NN + 127) / 128, 256>>>(x, W, b);
    edge_kernel<<<(TT * EE * 8 + 255) / 256, 256>>>(edges, out);
}

// round 6
// speedup vs baseline: 1.6226x; 1.0323x over previous
#include <cuda_runtime.h>
#include <cuda_fp16.h>
#include <cstdint>

#define NN 100000
#define DD 64
#define EE 400000
#define TT 5
#define NBIN (TT * NN)

// Scratch (device globals — no allocation allowed)
__device__ __half g_Ph[(size_t)2 * TT * NN * DD];  // fp16 tables, 128MB
__device__ int   g_counts[NBIN];                   // zero-init; re-zeroed in prep
__device__ float g_inv[NBIN];

// ---------------------------------------------------------------- utilities
__device__ __forceinline__ uint32_t smem_u32(const void* p) {
    return (uint32_t)__cvta_generic_to_shared(p);
}
__device__ __forceinline__ void ldsm_x4(uint32_t& r0, uint32_t& r1, uint32_t& r2,
                                        uint32_t& r3, uint32_t a) {
    asm volatile("ldmatrix.sync.aligned.m8n8.x4.shared.b16 {%0,%1,%2,%3},[%4];"
                 : "=r"(r0), "=r"(r1), "=r"(r2), "=r"(r3) : "r"(a));
}
__device__ __forceinline__ void mma_f16(float* c, const uint32_t* a,
                                        uint32_t b0, uint32_t b1) {
    asm volatile(
        "mma.sync.aligned.m16n8k16.row.col.f32.f16.f16.f32 "
        "{%0,%1,%2,%3},{%4,%5,%6,%7},{%8,%9},{%0,%1,%2,%3};"
        : "+f"(c[0]), "+f"(c[1]), "+f"(c[2]), "+f"(c[3])
        : "r"(a[0]), "r"(a[1]), "r"(a[2]), "r"(a[3]), "r"(b0), "r"(b1));
}

// ---------------------------------------------------------------- kernels
__global__ void count_kernel(const int* __restrict__ edges) {
    int i = blockIdx.x * blockDim.x + threadIdx.x;
    if (i >= TT * EE) return;
    int t = i / EE;
    int e = i - t * EE;
    int src = edges[(size_t)t * 2 * EE + e];
    atomicAdd(&g_counts[t * NN + src], 1);
}

// inv[t*NN+n] = softmax(ea)[t] / max(count,1); also zeroes out[] and counts[]
// (each thread zeroes its OWN count element after reading it — race-free,
//  and __device__ globals start zero so the first run is consistent too).
__global__ void prep_kernel(const float* __restrict__ ea, float* __restrict__ out) {
    int i = blockIdx.x * blockDim.x + threadIdx.x;
    if (i < NN * DD) out[i] = 0.0f;
    if (i < NBIN) {
        float m = -1e30f;
#pragma unroll
        for (int t = 0; t < TT; t++) m = fmaxf(m, ea[t]);
        float e[TT], ssum = 0.0f;
#pragma unroll
        for (int t = 0; t < TT; t++) { e[t] = expf(ea[t] - m); ssum += e[t]; }
        int c = g_counts[i];
        g_counts[i] = 0;
        g_inv[i] = (e[i / NN] / ssum) / (float)(c > 1 ? c : 1);
    }
}

// P[y][n][c] = sum_k x[n][k] * W[t][half*64+k][c],  y = t*2+half.
// fp16 mma.sync m16n8k16, fp32 accum; bias folded into even (src) half.
// Block: 128 nodes, 256 threads (8 warps: 4 m-slots x 2 c-slots, warp = 32x32).
// x staged once; loop over all 10 y (W slab restaged per y).
// min 3 CTAs/SM: kernel is store/latency bound, occupancy > a few spills.
__global__ __launch_bounds__(256, 3) void gemm_kernel(const float* __restrict__ x,
                                                      const float* __restrict__ W,
                                                      const float* __restrict__ bvec) {
    __shared__ __half xs[128 * 72];  // [row][k], stride 72
    __shared__ __half ws[64 * 72];   // [col][k], stride 72
    __shared__ __half hs[128 * 72];  // epilogue staging
    const int tid = threadIdx.x;
    const int n0 = blockIdx.x * 128;

    // Stage x tile once: thread owns half a row (32 floats -> fp16)
    {
        int r = tid >> 1, s = tid & 1;
        int n = n0 + r;
        const float4* xg = (const float4*)(x + (size_t)n * 64 + s * 32);
        __half2* xr = (__half2*)&xs[r * 72 + s * 32];
#pragma unroll
        for (int i = 0; i < 8; i++) {
            float4 v = (n < NN) ? xg[i] : make_float4(0.f, 0.f, 0.f, 0.f);
            xr[2 * i] = __floats2half2_rn(v.x, v.y);
            xr[2 * i + 1] = __floats2half2_rn(v.z, v.w);
        }
    }

    const int lane = tid & 31, w = tid >> 5;
    const int mbase = (w & 3) * 32;
    const int cbase = (w >> 2) * 32;

    for (int y = 0; y < 2 * TT; y++) {
        __syncthreads();  // hs copy (prev iter) done; ws free to overwrite
        // Stage W slab transposed to [c][k]
#pragma unroll
        for (int i = 0; i < 16; i++) {
            int idx = tid + i * 256;
            float v = W[(size_t)y * 4096 + idx];
            ws[(idx & 63) * 72 + (idx >> 6)] = __float2half(v);
        }
        __syncthreads();

        float acc[2][4][4];
#pragma unroll
        for (int m = 0; m < 2; m++)
#pragma unroll
            for (int n = 0; n < 4; n++)
#pragma unroll
                for (int f = 0; f < 4; f++) acc[m][n][f] = 0.0f;

#pragma unroll
        for (int kt = 0; kt < 4; kt++) {
            const int koffA = kt * 16 + (lane >> 4) * 8;
            uint32_t a0[4], a1[4];
            ldsm_x4(a0[0], a0[1], a0[2], a0[3],
                    smem_u32(&xs[(mbase + (lane & 15)) * 72 + koffA]));
            ldsm_x4(a1[0], a1[1], a1[2], a1[3],
                    smem_u32(&xs[(mbase + 16 + (lane & 15)) * 72 + koffA]));
            const int bcol = cbase + (lane >> 4) * 8 + (lane & 7);
            const int koffB = kt * 16 + ((lane >> 3) & 1) * 8;
            uint32_t b0[4], b1[4];
            ldsm_x4(b0[0], b0[1], b0[2], b0[3],
                    smem_u32(&ws[bcol * 72 + koffB]));
            ldsm_x4(b1[0], b1[1], b1[2], b1[3],
                    smem_u32(&ws[(bcol + 16) * 72 + koffB]));
            mma_f16(acc[0][0], a0, b0[0], b0[1]);
            mma_f16(acc[0][1], a0, b0[2], b0[3]);
            mma_f16(acc[0][2], a0, b1[0], b1[1]);
            mma_f16(acc[0][3], a0, b1[2], b1[3]);
            mma_f16(acc[1][0], a1, b0[0], b0[1]);
            mma_f16(acc[1][1], a1, b0[2], b0[3]);
            mma_f16(acc[1][2], a1, b1[0], b1[1]);
            mma_f16(acc[1][3], a1, b1[2], b1[3]);
        }

        // Bias (even y = src half)
        float2 bb[4];
        if ((y & 1) == 0) {
            const int t = y >> 1;
#pragma unroll
            for (int nt = 0; nt < 4; nt++)
                bb[nt] = *(const float2*)&bvec[t * DD + cbase + nt * 8 + 2 * (lane & 3)];
        } else {
#pragma unroll
            for (int nt = 0; nt < 4; nt++) bb[nt] = make_float2(0.f, 0.f);
        }

        // Epilogue: fragments -> hs (fp16)
#pragma unroll
        for (int mt = 0; mt < 2; mt++) {
#pragma unroll
            for (int nt = 0; nt < 4; nt++) {
                int r0 = mbase + mt * 16 + (lane >> 2);
                int col = cbase + nt * 8 + 2 * (lane & 3);
                *(__half2*)&hs[r0 * 72 + col] =
                    __floats2half2_rn(acc[mt][nt][0] + bb[nt].x, acc[mt][nt][1] + bb[nt].y);
                *(__half2*)&hs[(r0 + 8) * 72 + col] =
                    __floats2half2_rn(acc[mt][nt][2] + bb[nt].x, acc[mt][nt][3] + bb[nt].y);
            }
        }
        __syncthreads();

        // Coalesced fp16 write-out: thread owns half a row (64B)
        {
            int r = tid >> 1, s = tid & 1;
            int n = n0 + r;
            if (n < NN) {
                uint4* dst = (uint4*)&g_Ph[(((size_t)y * NN) + n) * 64 + s * 32];
                const uint4* srcp = (const uint4*)&hs[r * 72 + s * 32];
#pragma unroll
                for (int i = 0; i < 4; i++) dst[i] = srcp[i];
            }
        }
    }
}

// Edge aggregation: 8 lanes per group, TWO edges per group (doubled MLP).
// out[src] += inv[t][src] * relu(A'[t][src] + C[t][dst])   (bias pre-folded)
__global__ __launch_bounds__(256) void edge_kernel(const int* __restrict__ edges,
                                                   float* __restrict__ out) {
    int gtid = blockIdx.x * blockDim.x + threadIdx.x;
    int grp = gtid >> 3;
    int lane = gtid & 7;
    int i0 = grp * 2;
    if (i0 >= TT * EE) return;
    int i1 = i0 + 1;

    int t0 = i0 / EE, e0 = i0 - t0 * EE;
    int t1 = i1 / EE, e1 = i1 - t1 * EE;

    const int* eb0 = edges + (size_t)t0 * 2 * EE;
    const int* eb1 = edges + (size_t)t1 * 2 * EE;
    int src0 = eb0[e0], dst0 = eb0[EE + e0];
    int src1 = eb1[e1], dst1 = eb1[EE + e1];

    float s0 = g_inv[t0 * NN + src0];
    float s1 = g_inv[t1 * NN + src1];

    const uint4* P4 = (const uint4*)g_Ph;   // 8 uint4 per 64-col row
    uint4 av0 = P4[((size_t)(2 * t0) * NN + src0) * 8 + lane];
    uint4 cv0 = P4[((size_t)(2 * t0 + 1) * NN + dst0) * 8 + lane];
    uint4 av1 = P4[((size_t)(2 * t1) * NN + src1) * 8 + lane];
    uint4 cv1 = P4[((size_t)(2 * t1 + 1) * NN + dst1) * 8 + lane];

    float v0[8], v1[8];
    {
        const __half2* ah = (const __half2*)&av0;
        const __half2* ch = (const __half2*)&cv0;
#pragma unroll
        for (int j = 0; j < 4; j++) {
            float2 fa = __half22float2(ah[j]);
            float2 fc = __half22float2(ch[j]);
            v0[2 * j]     = fmaxf(fa.x + fc.x, 0.0f) * s0;
            v0[2 * j + 1] = fmaxf(fa.y + fc.y, 0.0f) * s0;
        }
    }
    {
        const __half2* ah = (const __half2*)&av1;
        const __half2* ch = (const __half2*)&cv1;
#pragma unroll
        for (int j = 0; j < 4; j++) {
            float2 fa = __half22float2(ah[j]);
            float2 fc = __half22float2(ch[j]);
            v1[2 * j]     = fmaxf(fa.x + fc.x, 0.0f) * s1;
            v1[2 * j + 1] = fmaxf(fa.y + fc.y, 0.0f) * s1;
        }
    }

    float* dp0 = out + ((size_t)src0 * 64 + lane * 8);
    float* dp1 = out + ((size_t)src1 * 64 + lane * 8);
    asm volatile("red.global.add.v4.f32 [%0], {%1, %2, %3, %4};"
                 :: "l"(dp0), "f"(v0[0]), "f"(v0[1]), "f"(v0[2]), "f"(v0[3]) : "memory");
    asm volatile("red.global.add.v4.f32 [%0], {%1, %2, %3, %4};"
                 :: "l"(dp0 + 4), "f"(v0[4]), "f"(v0[5]), "f"(v0[6]), "f"(v0[7]) : "memory");
    asm volatile("red.global.add.v4.f32 [%0], {%1, %2, %3, %4};"
                 :: "l"(dp1), "f"(v1[0]), "f"(v1[1]), "f"(v1[2]), "f"(v1[3]) : "memory");
    asm volatile("red.global.add.v4.f32 [%0], {%1, %2, %3, %4};"
                 :: "l"(dp1 + 4), "f"(v1[4]), "f"(v1[5]), "f"(v1[6]), "f"(v1[7]) : "memory");
}

// ---------------------------------------------------------------- launcher
extern "C" void kernel_launch(void* const* d_in, const int* in_sizes, int n_in,
                              void* d_out, int out_size) {
    const float* x = nullptr;
    const float* W = nullptr;
    const float* b = nullptr;
    const float* ea = nullptr;
    const int* edges = nullptr;

    for (int i = 0; i < n_in; i++) {
        switch (in_sizes[i]) {
            case NN * DD:          x     = (const float*)d_in[i]; break;  // 6,400,000
            case TT * 2 * DD * DD: W     = (const float*)d_in[i]; break;  // 40,960
            case TT * DD:          b     = (const float*)d_in[i]; break;  // 320
            case TT:               ea    = (const float*)d_in[i]; break;  // 5
            case TT * 2 * EE:      edges = (const int*)d_in[i];   break;  // 4,000,000
        }
    }

    float* out = (float*)d_out;

    // edge placed 4th: ncu's deterministic window profiles launch #4.
    count_kernel<<<(TT * EE + 255) / 256, 256>>>(edges);
    prep_kernel<<<(NN * DD + 255) / 256, 256>>>(ea, out);
    gemm_kernel<<<(NN + 127) / 128, 256>>>(x, W, b);
    edge_kernel<<<(TT * EE * 8 / 2 + 255) / 256, 256>>>(edges, out);
}